// round 13
// baseline (speedup 1.0000x reference)
#include <cuda_runtime.h>
#include <cstdint>

// SobelEdge3D: out = sqrt(ed^2 + eh^2 + ew^2 + 1e-6), separable Sobel.
// Round-13: R12 (h-first consumer) + paired-plane iterations: one
// wait_group + one __syncthreads per 2 planes, 8-slot ring (40KB),
// pair-granular cp.async groups. Thread = 4 w (float4) x 2 h x 16 d.

constexpr int Wd  = 128;
constexpr int Hd  = 128;
constexpr int Dd  = 64;
constexpr int BCn = 32;          // B*C = 2*16
constexpr int HT  = 8;           // output h rows per block
constexpr int ND  = 16;          // d outputs per block
constexpr int HW  = Hd * Wd;
constexpr int NSLOT = 8;         // ring slots (4 pairs)
constexpr int SROWS = HT + 2;    // 10 tile rows: h0-1 .. h0+8
constexpr int NPL   = ND + 2;    // 18 planes consumed per block (9 pairs)

__device__ __forceinline__ float sqrt_approx(float v) {
    float r; asm("sqrt.approx.f32 %0,%1;" : "=f"(r) : "f"(v)); return r;
}
__device__ __forceinline__ void cp16(uint32_t dst, const float* src, int sz) {
    // 16B async copy; sz=0 => zero-fill (padding rows/planes).
    asm volatile("cp.async.ca.shared.global [%0], [%1], 16, %2;"
                 :: "r"(dst), "l"(src), "r"(sz));
}
__device__ __forceinline__ void cp_commit() {
    asm volatile("cp.async.commit_group;" ::: "memory");
}
__device__ __forceinline__ void cp_wait2() {
    asm volatile("cp.async.wait_group 2;" ::: "memory");
}

__global__ __launch_bounds__(128, 5)
void sobel3d_kernel(const float* __restrict__ x, float* __restrict__ out)
{
    // Shared plane ring: plane k lives in slot k%8. 8 x 10 x 128 f32 = 40 KB.
    __shared__ alignas(16) float tile[NSLOT][SROWS][Wd];

    const int tid = threadIdx.x;
    const int tx  = tid & 31;                 // w = 4*tx .. 4*tx+3
    const int ty  = tid >> 5;                 // 0..3
    const int h0  = blockIdx.x * HT;
    const int d0  = blockIdx.y * ND;

    const float* __restrict__ xb = x   + (size_t)blockIdx.z * (Dd * HW);
    float* __restrict__       ob = out + (size_t)blockIdx.z * (Dd * HW);

    const uint32_t tb = (uint32_t)__cvta_generic_to_shared(tile) + (tx << 4);

    // Produce plane pair p (planes 2p, 2p+1 = d indices d0-1+2p, d0+2p) as ONE
    // cp.async group. Thread writes rows ty+4j (j=0,1[,2 if ty<2]) per plane.
    auto cp_pair = [&](int p) {
        if (2 * p >= NPL) { cp_commit(); return; }   // tail: empty group
        #pragma unroll
        for (int e = 0; e < 2; ++e) {
            const int k  = 2 * p + e;
            const int pd = d0 - 1 + k;
            const int pc = min(max(pd, 0), Dd - 1);  // clamped (addr safety)
            const bool pv = (unsigned)pd < (unsigned)Dd;
            const float* pb = xb + pc * HW + (tx << 2);
            const uint32_t db = tb + (k & (NSLOT - 1)) * (SROWS * Wd * 4);
            #pragma unroll
            for (int j = 0; j < 3; ++j) {
                const int r = ty + 4 * j;            // tile row
                if (r < SROWS) {
                    const int hh = h0 - 1 + r;       // global h of tile row r
                    const int hc = min(max(hh, 0), Hd - 1);
                    const int sz = (pv && (unsigned)hh < (unsigned)Hd) ? 16 : 0;
                    cp16(db + r * (Wd * 4), pb + hc * Wd, sz);
                }
            }
        }
        cp_commit();
    };

    // Read plane k's 4 rows and fold h-first to A/B/C (no wait/barrier here).
    auto abc = [&](int k, float (&A)[2][4], float (&B)[2][4], float (&C)[2][4]) {
        const int s = k & (NSLOT - 1);
        float q[4][4];
        #pragma unroll
        for (int r = 0; r < 4; ++r) {
            // tile row (2ty + r) = global h row h0+2ty-1+r (pads zeroed)
            float4 v = *(const float4*)&tile[s][(ty << 1) + r][tx << 2];
            q[r][0] = v.x; q[r][1] = v.y; q[r][2] = v.z; q[r][3] = v.w;
        }
        float hs[2][4], hg[2][4];
        #pragma unroll
        for (int j = 0; j < 4; ++j) {
            hs[0][j] = fmaf(2.f, q[1][j], q[0][j] + q[2][j]);
            hg[0][j] = q[2][j] - q[0][j];
            hs[1][j] = fmaf(2.f, q[2][j], q[1][j] + q[3][j]);
            hg[1][j] = q[3][j] - q[1][j];
        }
        #pragma unroll
        for (int o = 0; o < 2; ++o) {
            float lfs = __shfl_up_sync(0xffffffffu, hs[o][3], 1);
            float rts = __shfl_down_sync(0xffffffffu, hs[o][0], 1);
            float lfg = __shfl_up_sync(0xffffffffu, hg[o][3], 1);
            float rtg = __shfl_down_sync(0xffffffffu, hg[o][0], 1);
            if (tx == 0)  { lfs = 0.f; lfg = 0.f; }   // zero pad w = -1
            if (tx == 31) { rts = 0.f; rtg = 0.f; }   // zero pad w = 128
            A[o][0] = hs[o][1] - lfs;
            A[o][1] = hs[o][2] - hs[o][0];
            A[o][2] = hs[o][3] - hs[o][1];
            A[o][3] = rts      - hs[o][2];
            B[o][0] = fmaf(2.f, hg[o][0], lfg      + hg[o][1]);
            B[o][1] = fmaf(2.f, hg[o][1], hg[o][0] + hg[o][2]);
            B[o][2] = fmaf(2.f, hg[o][2], hg[o][1] + hg[o][3]);
            B[o][3] = fmaf(2.f, hg[o][3], hg[o][2] + rtg);
            C[o][0] = fmaf(2.f, hs[o][0], lfs      + hs[o][1]);
            C[o][1] = fmaf(2.f, hs[o][1], hs[o][0] + hs[o][2]);
            C[o][2] = fmaf(2.f, hs[o][2], hs[o][1] + hs[o][3]);
            C[o][3] = fmaf(2.f, hs[o][3], hs[o][2] + rts);
        }
    };

    float a[2][4], b[2][4], c[2][4];
    float ed0[2][4], eh0[2][4], ed1[2][4], eh1[2][4], Cp[2][4], Cq[2][4];

    // Prologue: pairs 0,1,2 in flight (planes 0..5; prefetch distance 4-6).
    cp_pair(0); cp_pair(1); cp_pair(2);

    // Iteration 0: consume pair 0 (planes d0-1, d0) = accumulator init.
    cp_wait2();
    __syncthreads();
    abc(0, a, b, c);
    #pragma unroll
    for (int o = 0; o < 2; ++o)
        #pragma unroll
        for (int j = 0; j < 4; ++j) {
            ed0[o][j] = a[o][j]; eh0[o][j] = b[o][j]; Cp[o][j] = c[o][j];
        }
    abc(1, a, b, c);
    #pragma unroll
    for (int o = 0; o < 2; ++o)
        #pragma unroll
        for (int j = 0; j < 4; ++j) {
            ed0[o][j] = fmaf(2.f, a[o][j], ed0[o][j]);
            eh0[o][j] = fmaf(2.f, b[o][j], eh0[o][j]);
            ed1[o][j] = a[o][j]; eh1[o][j] = b[o][j]; Cq[o][j] = c[o][j];
        }
    cp_pair(3);

    const int obase = d0 * HW + (h0 + (ty << 1)) * Wd + (tx << 2);

    // Emit for output index i given this plane's (a,b,c) = plane i+1 data.
    auto emit = [&](int i) {
        #pragma unroll
        for (int o = 0; o < 2; ++o) {
            float res[4];
            #pragma unroll
            for (int j = 0; j < 4; ++j) {
                float ed = ed0[o][j] + a[o][j];
                float eh = eh0[o][j] + b[o][j];
                float ew = c[o][j] - Cp[o][j];
                float m  = fmaf(ew, ew, fmaf(eh, eh, fmaf(ed, ed, 1e-6f)));
                res[j] = sqrt_approx(m);
                ed0[o][j] = fmaf(2.f, a[o][j], ed1[o][j]);
                eh0[o][j] = fmaf(2.f, b[o][j], eh1[o][j]);
                ed1[o][j] = a[o][j];
                eh1[o][j] = b[o][j];
                Cp[o][j]  = Cq[o][j];
                Cq[o][j]  = c[o][j];
            }
            *(float4*)(ob + obase + i * HW + o * Wd) =
                make_float4(res[0], res[1], res[2], res[3]);
        }
    };

    // Steady state: iter j consumes planes 2j, 2j+1 (outputs 2j-2, 2j-1),
    // then refills pair j+3 (overwrites pair j-1's slots, read last iter).
    #pragma unroll
    for (int j = 1; j <= 8; ++j) {
        cp_wait2();
        __syncthreads();
        abc(2 * j, a, b, c);
        emit(2 * j - 2);
        abc(2 * j + 1, a, b, c);
        emit(2 * j - 1);
        cp_pair(j + 3);              // empty group past pair 8
    }
}

extern "C" void kernel_launch(void* const* d_in, const int* in_sizes, int n_in,
                              void* d_out, int out_size)
{
    const float* x = (const float*)d_in[0];
    float* out = (float*)d_out;
    dim3 grid(Hd / HT, Dd / ND, BCn);   // (16, 4, 32) = 2048 blocks
    dim3 block(128);                    // 4 warps; thread = 4w x 2h x 16d
    sobel3d_kernel<<<grid, block>>>(x, out);
}

// round 14
// speedup vs baseline: 1.1669x; 1.1669x over previous
#include <cuda_runtime.h>
#include <cstdint>

// SobelEdge3D: out = sqrt(ed^2 + eh^2 + ew^2 + 1e-6), separable Sobel.
// Round-14: R12 + consumer software pipelining: emit is delayed one plane so
// it becomes independent work covering the LDS/SHFL latency of the current
// plane. Iter: wait/bar -> LDS k -> cp_plane -> h-stage -> shfl -> emit(i-1)
// from held aP/bP/cP -> w-stage k -> aP/bP/cP. Tail emit after loop.
// Thread = 4 w (float4) x 2 h rows x 16 d. 20KB ring, depth 4.

constexpr int Wd  = 128;
constexpr int Hd  = 128;
constexpr int Dd  = 64;
constexpr int BCn = 32;          // B*C = 2*16
constexpr int HT  = 8;           // output h rows per block
constexpr int ND  = 16;          // d outputs per block
constexpr int HW  = Hd * Wd;
constexpr int NSLOT = 4;         // ring depth
constexpr int SROWS = HT + 2;    // 10 tile rows: h0-1 .. h0+8
constexpr int NPL   = ND + 2;    // 18 planes consumed per block

__device__ __forceinline__ float sqrt_approx(float v) {
    float r; asm("sqrt.approx.f32 %0,%1;" : "=f"(r) : "f"(v)); return r;
}
__device__ __forceinline__ void cp16(uint32_t dst, const float* src, int sz) {
    asm volatile("cp.async.ca.shared.global [%0], [%1], 16, %2;"
                 :: "r"(dst), "l"(src), "r"(sz));
}
__device__ __forceinline__ void cp_commit() {
    asm volatile("cp.async.commit_group;" ::: "memory");
}
__device__ __forceinline__ void cp_wait2() {
    asm volatile("cp.async.wait_group 2;" ::: "memory");
}

__global__ __launch_bounds__(128, 5)
void sobel3d_kernel(const float* __restrict__ x, float* __restrict__ out)
{
    __shared__ alignas(16) float tile[NSLOT][SROWS][Wd];   // 20 KB

    const int tid = threadIdx.x;
    const int tx  = tid & 31;                 // w = 4*tx .. 4*tx+3
    const int ty  = tid >> 5;                 // 0..3
    const int h0  = blockIdx.x * HT;
    const int d0  = blockIdx.y * ND;

    const float* __restrict__ xb = x   + (size_t)blockIdx.z * (Dd * HW);
    float* __restrict__       ob = out + (size_t)blockIdx.z * (Dd * HW);

    const uint32_t tb = (uint32_t)__cvta_generic_to_shared(tile) + (tx << 4);

    // Produce plane k (= d-index d0-1+k) into slot k&3; always commits.
    auto cp_plane = [&](int k) {
        if (k >= NPL) { cp_commit(); return; }     // tail: empty group
        const int p  = d0 - 1 + k;
        const int pc = min(max(p, 0), Dd - 1);     // clamped (addr safety)
        const bool pv = (unsigned)p < (unsigned)Dd;
        const float* pb = xb + pc * HW + (tx << 2);
        const uint32_t db = tb + (k & (NSLOT - 1)) * (SROWS * Wd * 4);
        #pragma unroll
        for (int j = 0; j < 3; ++j) {
            const int r = ty + 4 * j;              // tile row
            if (r < SROWS) {
                const int hh = h0 - 1 + r;         // global h of tile row r
                const int hc = min(max(hh, 0), Hd - 1);
                const int sz = (pv && (unsigned)hh < (unsigned)Hd) ? 16 : 0;
                cp16(db + r * (Wd * 4), pb + hc * Wd, sz);
            }
        }
        cp_commit();
    };

    // Load plane k's 4 rows (after wait+barrier done by caller).
    auto ldq = [&](int k, float (&q)[4][4]) {
        const int s = k & (NSLOT - 1);
        #pragma unroll
        for (int r = 0; r < 4; ++r) {
            float4 v = *(const float4*)&tile[s][(ty << 1) + r][tx << 2];
            q[r][0] = v.x; q[r][1] = v.y; q[r][2] = v.z; q[r][3] = v.w;
        }
    };

    auto hstage = [&](const float (&q)[4][4],
                      float (&hs)[2][4], float (&hg)[2][4]) {
        #pragma unroll
        for (int j = 0; j < 4; ++j) {
            hs[0][j] = fmaf(2.f, q[1][j], q[0][j] + q[2][j]);
            hg[0][j] = q[2][j] - q[0][j];
            hs[1][j] = fmaf(2.f, q[2][j], q[1][j] + q[3][j]);
            hg[1][j] = q[3][j] - q[1][j];
        }
    };

    // Issue the 8 halo shuffles + pad selects (results consumed later).
    auto wshfl = [&](const float (&hs)[2][4], const float (&hg)[2][4],
                     float (&lfs)[2], float (&rts)[2],
                     float (&lfg)[2], float (&rtg)[2]) {
        #pragma unroll
        for (int o = 0; o < 2; ++o) {
            lfs[o] = __shfl_up_sync(0xffffffffu, hs[o][3], 1);
            rts[o] = __shfl_down_sync(0xffffffffu, hs[o][0], 1);
            lfg[o] = __shfl_up_sync(0xffffffffu, hg[o][3], 1);
            rtg[o] = __shfl_down_sync(0xffffffffu, hg[o][0], 1);
            if (tx == 0)  { lfs[o] = 0.f; lfg[o] = 0.f; }  // pad w = -1
            if (tx == 31) { rts[o] = 0.f; rtg[o] = 0.f; }  // pad w = 128
        }
    };

    auto wstage = [&](const float (&hs)[2][4], const float (&hg)[2][4],
                      const float (&lfs)[2], const float (&rts)[2],
                      const float (&lfg)[2], const float (&rtg)[2],
                      float (&A)[2][4], float (&B)[2][4], float (&C)[2][4]) {
        #pragma unroll
        for (int o = 0; o < 2; ++o) {
            A[o][0] = hs[o][1] - lfs[o];
            A[o][1] = hs[o][2] - hs[o][0];
            A[o][2] = hs[o][3] - hs[o][1];
            A[o][3] = rts[o]   - hs[o][2];
            B[o][0] = fmaf(2.f, hg[o][0], lfg[o]   + hg[o][1]);
            B[o][1] = fmaf(2.f, hg[o][1], hg[o][0] + hg[o][2]);
            B[o][2] = fmaf(2.f, hg[o][2], hg[o][1] + hg[o][3]);
            B[o][3] = fmaf(2.f, hg[o][3], hg[o][2] + rtg[o]);
            C[o][0] = fmaf(2.f, hs[o][0], lfs[o]   + hs[o][1]);
            C[o][1] = fmaf(2.f, hs[o][1], hs[o][0] + hs[o][2]);
            C[o][2] = fmaf(2.f, hs[o][2], hs[o][1] + hs[o][3]);
            C[o][3] = fmaf(2.f, hs[o][3], hs[o][2] + rts[o]);
        }
    };

    // Persistent state.
    float aP[2][4], bP[2][4], cP[2][4];                       // held plane abc
    float ed0[2][4], eh0[2][4], ed1[2][4], eh1[2][4], Cp[2][4], Cq[2][4];

    const int obase = d0 * HW + (h0 + (ty << 1)) * Wd + (tx << 2);

    // Emit output i from held aP/bP/cP (= plane i+1) + accumulators; update.
    auto emit = [&](int i) {
        #pragma unroll
        for (int o = 0; o < 2; ++o) {
            float res[4];
            #pragma unroll
            for (int j = 0; j < 4; ++j) {
                float ed = ed0[o][j] + aP[o][j];
                float eh = eh0[o][j] + bP[o][j];
                float ew = cP[o][j] - Cp[o][j];
                float m  = fmaf(ew, ew, fmaf(eh, eh, fmaf(ed, ed, 1e-6f)));
                res[j] = sqrt_approx(m);
                ed0[o][j] = fmaf(2.f, aP[o][j], ed1[o][j]);
                eh0[o][j] = fmaf(2.f, bP[o][j], eh1[o][j]);
                ed1[o][j] = aP[o][j];
                eh1[o][j] = bP[o][j];
                Cp[o][j]  = Cq[o][j];
                Cq[o][j]  = cP[o][j];
            }
            *(float4*)(ob + obase + i * HW + o * Wd) =
                make_float4(res[0], res[1], res[2], res[3]);
        }
    };

    // Prologue: pipeline fill.
    cp_plane(0); cp_plane(1); cp_plane(2);

    {   // plane k=0 (d0-1): accumulator init.
        float q[4][4], hs[2][4], hg[2][4], lfs[2], rts[2], lfg[2], rtg[2];
        cp_wait2(); __syncthreads();
        ldq(0, q);
        cp_plane(3);
        hstage(q, hs, hg);
        wshfl(hs, hg, lfs, rts, lfg, rtg);
        wstage(hs, hg, lfs, rts, lfg, rtg, aP, bP, cP);
        #pragma unroll
        for (int o = 0; o < 2; ++o)
            #pragma unroll
            for (int j = 0; j < 4; ++j) {
                ed0[o][j] = aP[o][j]; eh0[o][j] = bP[o][j]; Cp[o][j] = cP[o][j];
            }
    }
    {   // plane k=1 (d0): accumulator init part 2.
        float q[4][4], hs[2][4], hg[2][4], lfs[2], rts[2], lfg[2], rtg[2];
        cp_wait2(); __syncthreads();
        ldq(1, q);
        cp_plane(4);
        hstage(q, hs, hg);
        wshfl(hs, hg, lfs, rts, lfg, rtg);
        wstage(hs, hg, lfs, rts, lfg, rtg, aP, bP, cP);
        #pragma unroll
        for (int o = 0; o < 2; ++o)
            #pragma unroll
            for (int j = 0; j < 4; ++j) {
                ed0[o][j] = fmaf(2.f, aP[o][j], ed0[o][j]);
                eh0[o][j] = fmaf(2.f, bP[o][j], eh0[o][j]);
                ed1[o][j] = aP[o][j]; eh1[o][j] = bP[o][j]; Cq[o][j] = cP[o][j];
            }
    }

    // Steady: iter i consumes plane k=i+2; emit(i-1) fills the latency hole
    // between the shfl issue and the w-stage that consumes the shfl results.
    #pragma unroll
    for (int i = 0; i < ND; ++i) {
        float q[4][4], hs[2][4], hg[2][4], lfs[2], rts[2], lfg[2], rtg[2];
        cp_wait2(); __syncthreads();
        ldq(i + 2, q);
        cp_plane(i + 5);
        hstage(q, hs, hg);
        wshfl(hs, hg, lfs, rts, lfg, rtg);
        if (i > 0) emit(i - 1);     // independent work: covers shfl latency
        wstage(hs, hg, lfs, rts, lfg, rtg, aP, bP, cP);
    }
    emit(ND - 1);                   // tail: output 15 from plane 17's abc
}

extern "C" void kernel_launch(void* const* d_in, const int* in_sizes, int n_in,
                              void* d_out, int out_size)
{
    const float* x = (const float*)d_in[0];
    float* out = (float*)d_out;
    dim3 grid(Hd / HT, Dd / ND, BCn);   // (16, 4, 32) = 2048 blocks
    dim3 block(128);                    // 4 warps; thread = 4w x 2h x 16d
    sobel3d_kernel<<<grid, block>>>(x, out);
}

// round 15
// speedup vs baseline: 1.2640x; 1.0832x over previous
#include <cuda_runtime.h>
#include <cstdint>

// SobelEdge3D: out = sqrt(ed^2 + eh^2 + ew^2 + 1e-6), separable Sobel.
// Round-15: R12 (best) with two cache-policy changes only:
//   - cp.async.cg (L1-bypass) for the global->smem plane staging
//   - st.global.cs streaming stores for the pure-streaming output
// Structure identical to R12: shared plane tile (10 halo rows), depth-4
// cp.async ring, one __syncthreads per plane, h-first separable math.
// Thread = 4 w (float4) x 2 h rows x 16 d outputs.

constexpr int Wd  = 128;
constexpr int Hd  = 128;
constexpr int Dd  = 64;
constexpr int BCn = 32;          // B*C = 2*16
constexpr int HT  = 8;           // output h rows per block
constexpr int ND  = 16;          // d outputs per block
constexpr int HW  = Hd * Wd;
constexpr int NSLOT = 4;         // ring depth
constexpr int SROWS = HT + 2;    // 10 tile rows: h0-1 .. h0+8
constexpr int NPL   = ND + 2;    // 18 planes consumed per block

__device__ __forceinline__ float sqrt_approx(float v) {
    float r; asm("sqrt.approx.f32 %0,%1;" : "=f"(r) : "f"(v)); return r;
}
__device__ __forceinline__ void cp16(uint32_t dst, const float* src, int sz) {
    // 16B async copy, L1-bypass (.cg); sz=0 => zero-fill (padding).
    asm volatile("cp.async.cg.shared.global [%0], [%1], 16, %2;"
                 :: "r"(dst), "l"(src), "r"(sz));
}
__device__ __forceinline__ void cp_commit() {
    asm volatile("cp.async.commit_group;" ::: "memory");
}
__device__ __forceinline__ void cp_wait2() {
    asm volatile("cp.async.wait_group 2;" ::: "memory");
}
__device__ __forceinline__ void stcs128(float* p, float4 v) {
    asm volatile("st.global.cs.v4.f32 [%0], {%1,%2,%3,%4};"
                 :: "l"(p), "f"(v.x), "f"(v.y), "f"(v.z), "f"(v.w) : "memory");
}

__global__ __launch_bounds__(128, 5)
void sobel3d_kernel(const float* __restrict__ x, float* __restrict__ out)
{
    // Shared plane ring: 10 unique halo rows per plane, full 128-wide.
    __shared__ alignas(16) float tile[NSLOT][SROWS][Wd];   // 20 KB

    const int tid = threadIdx.x;
    const int tx  = tid & 31;                 // w = 4*tx .. 4*tx+3
    const int ty  = tid >> 5;                 // 0..3
    const int h0  = blockIdx.x * HT;
    const int d0  = blockIdx.y * ND;

    const float* __restrict__ xb = x   + (size_t)blockIdx.z * (Dd * HW);
    float* __restrict__       ob = out + (size_t)blockIdx.z * (Dd * HW);

    const uint32_t tb = (uint32_t)__cvta_generic_to_shared(tile);

    // Produce plane k (= d-index d0-1+k) into slot k&3.
    // Thread tid writes rows ty+4j (j=0,1[,2 if ty<2]) at column tx (16B).
    auto cp_plane = [&](int k) {
        if (k >= NPL) { cp_commit(); return; }     // tail: empty group
        const int p  = d0 - 1 + k;
        const int pc = min(max(p, 0), Dd - 1);     // clamped address (safety)
        const bool pv = (unsigned)p < (unsigned)Dd;
        const float* pb = xb + pc * HW + (tx << 2);
        const uint32_t db = tb + (k & (NSLOT - 1)) * (SROWS * Wd * 4) + (tx << 4);
        #pragma unroll
        for (int j = 0; j < 3; ++j) {
            const int r = ty + 4 * j;              // tile row
            if (r < SROWS) {
                const int hh = h0 - 1 + r;         // global h of tile row r
                const int hc = min(max(hh, 0), Hd - 1);
                const int sz = (pv && (unsigned)hh < (unsigned)Hd) ? 16 : 0;
                cp16(db + r * (Wd * 4), pb + hc * Wd, sz);
            }
        }
        cp_commit();
    };

    // Consume plane k: wait, block-sync, read 4 rows, h-first fold to A/B/C.
    auto abc = [&](int k, float (&A)[2][4], float (&B)[2][4], float (&C)[2][4]) {
        cp_wait2();
        __syncthreads();
        const int s = k & (NSLOT - 1);
        float q[4][4];
        #pragma unroll
        for (int r = 0; r < 4; ++r) {
            // tile row (2ty + r) = global h row h0+2ty-1+r (pads already zeroed)
            float4 v = *(const float4*)&tile[s][(ty << 1) + r][tx << 2];
            q[r][0] = v.x; q[r][1] = v.y; q[r][2] = v.z; q[r][3] = v.w;
        }
        // h-stage: hs[o] = s_h, hg[o] = g_h for output rows o=0,1.
        float hs[2][4], hg[2][4];
        #pragma unroll
        for (int j = 0; j < 4; ++j) {
            hs[0][j] = fmaf(2.f, q[1][j], q[0][j] + q[2][j]);
            hg[0][j] = q[2][j] - q[0][j];
            hs[1][j] = fmaf(2.f, q[2][j], q[1][j] + q[3][j]);
            hg[1][j] = q[3][j] - q[1][j];
        }
        // w-stage: A = g_w(hs), B = s_w(hg), C = s_w(hs).
        #pragma unroll
        for (int o = 0; o < 2; ++o) {
            float lfs = __shfl_up_sync(0xffffffffu, hs[o][3], 1);
            float rts = __shfl_down_sync(0xffffffffu, hs[o][0], 1);
            float lfg = __shfl_up_sync(0xffffffffu, hg[o][3], 1);
            float rtg = __shfl_down_sync(0xffffffffu, hg[o][0], 1);
            if (tx == 0)  { lfs = 0.f; lfg = 0.f; }   // zero pad w = -1
            if (tx == 31) { rts = 0.f; rtg = 0.f; }   // zero pad w = 128
            A[o][0] = hs[o][1] - lfs;
            A[o][1] = hs[o][2] - hs[o][0];
            A[o][2] = hs[o][3] - hs[o][1];
            A[o][3] = rts      - hs[o][2];
            B[o][0] = fmaf(2.f, hg[o][0], lfg      + hg[o][1]);
            B[o][1] = fmaf(2.f, hg[o][1], hg[o][0] + hg[o][2]);
            B[o][2] = fmaf(2.f, hg[o][2], hg[o][1] + hg[o][3]);
            B[o][3] = fmaf(2.f, hg[o][3], hg[o][2] + rtg);
            C[o][0] = fmaf(2.f, hs[o][0], lfs      + hs[o][1]);
            C[o][1] = fmaf(2.f, hs[o][1], hs[o][0] + hs[o][2]);
            C[o][2] = fmaf(2.f, hs[o][2], hs[o][1] + hs[o][3]);
            C[o][3] = fmaf(2.f, hs[o][3], hs[o][2] + rts);
        }
    };

    float a[2][4], b[2][4], c[2][4];
    float ed0[2][4], eh0[2][4], ed1[2][4], eh1[2][4], Cp[2][4], Cq[2][4];

    // Prologue: planes k = 0, 1, 2 in flight (prefetch distance 3).
    cp_plane(0); cp_plane(1); cp_plane(2);

    // Consume k=0 (plane d0-1); refill k=3.
    abc(0, a, b, c);
    #pragma unroll
    for (int o = 0; o < 2; ++o)
        #pragma unroll
        for (int j = 0; j < 4; ++j) {
            ed0[o][j] = a[o][j]; eh0[o][j] = b[o][j]; Cp[o][j] = c[o][j];
        }
    cp_plane(3);

    // Consume k=1 (plane d0); refill k=4.
    abc(1, a, b, c);
    #pragma unroll
    for (int o = 0; o < 2; ++o)
        #pragma unroll
        for (int j = 0; j < 4; ++j) {
            ed0[o][j] = fmaf(2.f, a[o][j], ed0[o][j]);
            eh0[o][j] = fmaf(2.f, b[o][j], eh0[o][j]);
            ed1[o][j] = a[o][j]; eh1[o][j] = b[o][j]; Cq[o][j] = c[o][j];
        }
    cp_plane(4);

    const int obase = d0 * HW + (h0 + (ty << 1)) * Wd + (tx << 2);

    // Steady state: iter i consumes k=i+2 (plane d0+1+i), refills k=i+5.
    #pragma unroll
    for (int i = 0; i < ND; ++i) {
        abc(i + 2, a, b, c);

        #pragma unroll
        for (int o = 0; o < 2; ++o) {
            float res[4];
            #pragma unroll
            for (int j = 0; j < 4; ++j) {
                float ed = ed0[o][j] + a[o][j];
                float eh = eh0[o][j] + b[o][j];
                float ew = c[o][j] - Cp[o][j];
                float m  = fmaf(ew, ew, fmaf(eh, eh, fmaf(ed, ed, 1e-6f)));
                res[j] = sqrt_approx(m);
                ed0[o][j] = fmaf(2.f, a[o][j], ed1[o][j]);
                eh0[o][j] = fmaf(2.f, b[o][j], eh1[o][j]);
                ed1[o][j] = a[o][j];
                eh1[o][j] = b[o][j];
                Cp[o][j]  = Cq[o][j];
                Cq[o][j]  = c[o][j];
            }
            stcs128(ob + obase + i * HW + o * Wd,
                    make_float4(res[0], res[1], res[2], res[3]));
        }
        cp_plane(i + 5);            // empty group past the last needed plane
    }
}

extern "C" void kernel_launch(void* const* d_in, const int* in_sizes, int n_in,
                              void* d_out, int out_size)
{
    const float* x = (const float*)d_in[0];
    float* out = (float*)d_out;
    dim3 grid(Hd / HT, Dd / ND, BCn);   // (16, 4, 32) = 2048 blocks
    dim3 block(128);                    // 4 warps; thread = 4w x 2h x 16d
    sobel3d_kernel<<<grid, block>>>(x, out);
}